// round 2
// baseline (speedup 1.0000x reference)
#include <cuda_runtime.h>
#include <cuda_bf16.h>

// ============================================================================
// MaskFunctionHaar: out = MLP(Haar(t)). All Haar edges are exact multiples of
// 2^-10 in fp32, so the full 1023-dim mask vector -- and hence the MLP output
// -- depends only on M = floor(t*1024) in [0,1024).
//   Kernel 1: evaluate the MLP for all 1024 M values -> 16KB float4 LUT.
//   Kernel 2: vectorized gather out[i] = LUT[M(t_i)], coalesced float4 stores.
// ============================================================================

__device__ float4 g_lut[1024];

__global__ void haar_prep_kernel(const float* __restrict__ W1,
                                 const float* __restrict__ b1,
                                 const float* __restrict__ W2,
                                 const float* __restrict__ b2,
                                 const float* __restrict__ W3,
                                 const float* __restrict__ b3) {
    int M = blockIdx.x * blockDim.x + threadIdx.x;
    if (M >= 1024) return;

    // layer 1: h1 = relu(b1 + sum_j sign_j * W1[idx_j, :])
    float h1[8];
#pragma unroll
    for (int h = 0; h < 8; ++h) h1[h] = __ldg(b1 + h);

#pragma unroll
    for (int j = 0; j < 10; ++j) {
        int idx = (1 << j) - 1 + (M >> (10 - j));      // active Haar basis, level j
        float s = ((M >> (9 - j)) & 1) ? -1.0f : 1.0f; // left half +1, right half -1
        const float* row = W1 + idx * 8;
#pragma unroll
        for (int h = 0; h < 8; ++h) h1[h] = fmaf(s, __ldg(row + h), h1[h]);
    }
#pragma unroll
    for (int h = 0; h < 8; ++h) h1[h] = fmaxf(h1[h], 0.0f);

    // layer 2: h2 = relu(h1 @ W2 + b2), W2 (8,8) row-major
    float h2[8];
#pragma unroll
    for (int k = 0; k < 8; ++k) {
        float v = __ldg(b2 + k);
#pragma unroll
        for (int h = 0; h < 8; ++h) v = fmaf(h1[h], __ldg(W2 + h * 8 + k), v);
        h2[k] = fmaxf(v, 0.0f);
    }

    // layer 3: o = h2 @ W3 + b3, W3 (8,3) row-major
    float o[3];
#pragma unroll
    for (int f = 0; f < 3; ++f) {
        float v = __ldg(b3 + f);
#pragma unroll
        for (int k = 0; k < 8; ++k) v = fmaf(h2[k], __ldg(W3 + k * 3 + f), v);
        o[f] = v;
    }

    g_lut[M] = make_float4(o[0], o[1], o[2], 0.0f);
}

// Each thread handles 8 samples: 2 float4 loads of t, 8 LUT gathers,
// 6 coalesced float4 stores (24 output floats).
__global__ void haar_apply_kernel(const float4* __restrict__ t4,
                                  float4* __restrict__ out4, int n4) {
    int i = (blockIdx.x * blockDim.x + threadIdx.x) * 2;
    if (i >= n4) return;

    const float4* __restrict__ lut = (const float4*)g_lut;

    float4 va = t4[i];
    float4 vb = t4[i + 1];

    unsigned m0 = min((unsigned)(int)(va.x * 1024.0f), 1023u);
    unsigned m1 = min((unsigned)(int)(va.y * 1024.0f), 1023u);
    unsigned m2 = min((unsigned)(int)(va.z * 1024.0f), 1023u);
    unsigned m3 = min((unsigned)(int)(va.w * 1024.0f), 1023u);
    unsigned m4 = min((unsigned)(int)(vb.x * 1024.0f), 1023u);
    unsigned m5 = min((unsigned)(int)(vb.y * 1024.0f), 1023u);
    unsigned m6 = min((unsigned)(int)(vb.z * 1024.0f), 1023u);
    unsigned m7 = min((unsigned)(int)(vb.w * 1024.0f), 1023u);

    float4 r0 = __ldg(lut + m0);
    float4 r1 = __ldg(lut + m1);
    float4 r2 = __ldg(lut + m2);
    float4 r3 = __ldg(lut + m3);
    float4 r4 = __ldg(lut + m4);
    float4 r5 = __ldg(lut + m5);
    float4 r6 = __ldg(lut + m6);
    float4 r7 = __ldg(lut + m7);

    out4[i * 3 + 0] = make_float4(r0.x, r0.y, r0.z, r1.x);
    out4[i * 3 + 1] = make_float4(r1.y, r1.z, r2.x, r2.y);
    out4[i * 3 + 2] = make_float4(r2.z, r3.x, r3.y, r3.z);
    out4[i * 3 + 3] = make_float4(r4.x, r4.y, r4.z, r5.x);
    out4[i * 3 + 4] = make_float4(r5.y, r5.z, r6.x, r6.y);
    out4[i * 3 + 5] = make_float4(r6.z, r7.x, r7.y, r7.z);
}

extern "C" void kernel_launch(void* const* d_in, const int* in_sizes, int n_in,
                              void* d_out, int out_size) {
    const float* t  = (const float*)d_in[0];
    const float* W1 = (const float*)d_in[1];
    const float* b1 = (const float*)d_in[2];
    const float* W2 = (const float*)d_in[3];
    const float* b2 = (const float*)d_in[4];
    const float* W3 = (const float*)d_in[5];
    const float* b3 = (const float*)d_in[6];
    float* out = (float*)d_out;

    int n  = in_sizes[0];   // B*T = 131072
    int n4 = n / 4;         // 32768 float4 loads of t
    int nthreads = n4 / 2;  // 8 samples per thread

    haar_prep_kernel<<<4, 256>>>(W1, b1, W2, b2, W3, b3);
    haar_apply_kernel<<<(nthreads + 255) / 256, 256>>>(
        (const float4*)t, (float4*)out, n4);
}

// round 3
// speedup vs baseline: 1.2399x; 1.2399x over previous
#include <cuda_runtime.h>
#include <cuda_bf16.h>

// ============================================================================
// MaskFunctionHaar, fully fused single kernel.
//
// All Haar edges are exact fp32 multiples of 2^-10, so the 1023-dim mask and
// hence the whole MLP output depend only on M = floor(t*1024) in [0,1024).
//
// Each block:
//   1) builds the 1024-entry float4 LUT in shared memory. Thread tid owns
//      M in {4*tid..4*tid+3}. Haar levels 0..7 depend only on M>>2 == tid,
//      so their partial sum P is computed once per thread; level 8's row is
//      also shared by the group (only its sign differs); level 9 contributes
//      one of two rows. This shrinks layer-1 work ~3x vs direct evaluation.
//   2) gathers: one float4 of t per thread -> 4 SMEM LUT lookups -> 3
//      float4 stores.
// ============================================================================

__device__ __forceinline__ void mlp_tail(const float h1in[8],
                                         const float* __restrict__ sW2,
                                         const float* __restrict__ sb2,
                                         const float* __restrict__ sW3,
                                         const float* __restrict__ sb3,
                                         float4* dst) {
    // relu on layer-1 preactivation
    float h1[8];
#pragma unroll
    for (int h = 0; h < 8; ++h) h1[h] = fmaxf(h1in[h], 0.0f);

    // layer 2: h2 = relu(h1 @ W2 + b2), W2 (8,8) row-major (SMEM broadcast)
    float h2[8];
#pragma unroll
    for (int k = 0; k < 8; ++k) h2[k] = sb2[k];
#pragma unroll
    for (int h = 0; h < 8; ++h) {
        float x = h1[h];
#pragma unroll
        for (int k = 0; k < 8; ++k) h2[k] = fmaf(x, sW2[h * 8 + k], h2[k]);
    }
#pragma unroll
    for (int k = 0; k < 8; ++k) h2[k] = fmaxf(h2[k], 0.0f);

    // layer 3: o = h2 @ W3 + b3, W3 (8,3) row-major
    float o0 = sb3[0], o1 = sb3[1], o2 = sb3[2];
#pragma unroll
    for (int k = 0; k < 8; ++k) {
        float x = h2[k];
        o0 = fmaf(x, sW3[k * 3 + 0], o0);
        o1 = fmaf(x, sW3[k * 3 + 1], o1);
        o2 = fmaf(x, sW3[k * 3 + 2], o2);
    }
    *dst = make_float4(o0, o1, o2, 0.0f);
}

__global__ __launch_bounds__(256, 1) void haar_fused_kernel(
    const float4* __restrict__ t4,
    const float* __restrict__ W1, const float* __restrict__ b1,
    const float* __restrict__ W2, const float* __restrict__ b2,
    const float* __restrict__ W3, const float* __restrict__ b3,
    float4* __restrict__ out4, int n4) {
    __shared__ float4 lut[1024];
    __shared__ float sW2[64];
    __shared__ float sW3[24];
    __shared__ float sb1[8], sb2[8], sb3[4];

    const int tid = threadIdx.x;

    // stage small weights into SMEM
    if (tid < 64) sW2[tid] = W2[tid];
    else if (tid < 88) sW3[tid - 64] = W3[tid - 64];
    else if (tid >= 96 && tid < 104) sb1[tid - 96] = b1[tid - 96];
    else if (tid >= 104 && tid < 112) sb2[tid - 104] = b2[tid - 104];
    else if (tid >= 112 && tid < 115) sb3[tid - 112] = b3[tid - 112];
    __syncthreads();

    // ---- build LUT: thread tid owns M in {4*tid .. 4*tid+3} ----
    // levels 0..7: depend only on tid (= M>>2)
    float P[8];
#pragma unroll
    for (int h = 0; h < 8; ++h) P[h] = sb1[h];

#pragma unroll
    for (int j = 0; j < 8; ++j) {
        int idx = (1 << j) - 1 + (tid >> (8 - j));
        float s = ((tid >> (7 - j)) & 1) ? -1.0f : 1.0f;
        const float4* row = (const float4*)(W1 + idx * 8);
        float4 a = __ldg(row);
        float4 c = __ldg(row + 1);
        P[0] = fmaf(s, a.x, P[0]); P[1] = fmaf(s, a.y, P[1]);
        P[2] = fmaf(s, a.z, P[2]); P[3] = fmaf(s, a.w, P[3]);
        P[4] = fmaf(s, c.x, P[4]); P[5] = fmaf(s, c.y, P[5]);
        P[6] = fmaf(s, c.z, P[6]); P[7] = fmaf(s, c.w, P[7]);
    }

    // level 8: row idx = 255 + tid (shared by the group; sign = bit1 of M)
    const float4* r8 = (const float4*)(W1 + (255 + tid) * 8);
    float4 a8 = __ldg(r8), c8 = __ldg(r8 + 1);
    float Qp[8], Qn[8];
    Qp[0] = P[0] + a8.x; Qp[1] = P[1] + a8.y; Qp[2] = P[2] + a8.z; Qp[3] = P[3] + a8.w;
    Qp[4] = P[4] + c8.x; Qp[5] = P[5] + c8.y; Qp[6] = P[6] + c8.z; Qp[7] = P[7] + c8.w;
    Qn[0] = P[0] - a8.x; Qn[1] = P[1] - a8.y; Qn[2] = P[2] - a8.z; Qn[3] = P[3] - a8.w;
    Qn[4] = P[4] - c8.x; Qn[5] = P[5] - c8.y; Qn[6] = P[6] - c8.z; Qn[7] = P[7] - c8.w;

    // level 9: rows 511+2*tid (evals 0,1) and 512+2*tid (evals 2,3);
    // sign = bit0 of M
    const float4* r9a = (const float4*)(W1 + (511 + 2 * tid) * 8);
    const float4* r9b = (const float4*)(W1 + (512 + 2 * tid) * 8);
    float4 aA = __ldg(r9a), cA = __ldg(r9a + 1);
    float4 aB = __ldg(r9b), cB = __ldg(r9b + 1);
    float RA[8] = {aA.x, aA.y, aA.z, aA.w, cA.x, cA.y, cA.z, cA.w};
    float RB[8] = {aB.x, aB.y, aB.z, aB.w, cB.x, cB.y, cB.z, cB.w};

    float h1[8];
#pragma unroll
    for (int h = 0; h < 8; ++h) h1[h] = Qp[h] + RA[h];
    mlp_tail(h1, sW2, sb2, sW3, sb3, &lut[4 * tid + 0]);
#pragma unroll
    for (int h = 0; h < 8; ++h) h1[h] = Qp[h] - RA[h];
    mlp_tail(h1, sW2, sb2, sW3, sb3, &lut[4 * tid + 1]);
#pragma unroll
    for (int h = 0; h < 8; ++h) h1[h] = Qn[h] + RB[h];
    mlp_tail(h1, sW2, sb2, sW3, sb3, &lut[4 * tid + 2]);
#pragma unroll
    for (int h = 0; h < 8; ++h) h1[h] = Qn[h] - RB[h];
    mlp_tail(h1, sW2, sb2, sW3, sb3, &lut[4 * tid + 3]);

    __syncthreads();

    // ---- gather: 1 float4 of t per thread -> 4 SMEM lookups -> 3 stores ----
    int g = blockIdx.x * 256 + tid;
    if (g < n4) {
        float4 v = __ldg(t4 + g);
        unsigned m0 = min((unsigned)(int)(v.x * 1024.0f), 1023u);
        unsigned m1 = min((unsigned)(int)(v.y * 1024.0f), 1023u);
        unsigned m2 = min((unsigned)(int)(v.z * 1024.0f), 1023u);
        unsigned m3 = min((unsigned)(int)(v.w * 1024.0f), 1023u);

        float4 r0 = lut[m0];
        float4 r1 = lut[m1];
        float4 r2 = lut[m2];
        float4 r3 = lut[m3];

        out4[g * 3 + 0] = make_float4(r0.x, r0.y, r0.z, r1.x);
        out4[g * 3 + 1] = make_float4(r1.y, r1.z, r2.x, r2.y);
        out4[g * 3 + 2] = make_float4(r2.z, r3.x, r3.y, r3.z);
    }
}

extern "C" void kernel_launch(void* const* d_in, const int* in_sizes, int n_in,
                              void* d_out, int out_size) {
    const float* t  = (const float*)d_in[0];
    const float* W1 = (const float*)d_in[1];
    const float* b1 = (const float*)d_in[2];
    const float* W2 = (const float*)d_in[3];
    const float* b2 = (const float*)d_in[4];
    const float* W3 = (const float*)d_in[5];
    const float* b3 = (const float*)d_in[6];
    float* out = (float*)d_out;

    int n  = in_sizes[0];           // B*T = 131072
    int n4 = n / 4;                 // 32768 float4 samples
    int grid = (n4 + 255) / 256;    // 128 blocks

    haar_fused_kernel<<<grid, 256>>>(
        (const float4*)t, W1, b1, W2, b2, W3, b3, (float4*)out, n4);
}